// round 16
// baseline (speedup 1.0000x reference)
#include <cuda_runtime.h>
#include <math.h>

#define S_LEN   2048
#define D_MODEL 2048
#define NH      32
#define DH      64
#define QKV_COLS (3 * D_MODEL)   // 6144

// Scratch (allocation-free rule: static __device__ globals)
__device__ float g_qkv[(size_t)S_LEN * QKV_COLS];   // [S, 3, H, Dh]
__device__ float g_attn[(size_t)S_LEN * D_MODEL];   // [S, H*Dh]

// ---------------------------------------------------------------------------
// tf32 helpers
// ---------------------------------------------------------------------------
__device__ __forceinline__ unsigned f2tf32(float x) {
    unsigned r;
    asm("cvt.rna.tf32.f32 %0, %1;" : "=r"(r) : "f"(x));
    return r;
}

__device__ __forceinline__ void mma_tf32(float* d, const unsigned* a, const unsigned* b) {
    asm volatile(
        "mma.sync.aligned.m16n8k8.row.col.f32.tf32.tf32.f32 "
        "{%0,%1,%2,%3}, {%4,%5,%6,%7}, {%8,%9}, {%0,%1,%2,%3};\n"
        : "+f"(d[0]), "+f"(d[1]), "+f"(d[2]), "+f"(d[3])
        : "r"(a[0]), "r"(a[1]), "r"(a[2]), "r"(a[3]), "r"(b[0]), "r"(b[1]));
}

// ---------------------------------------------------------------------------
// Tensor-core GEMM NT (3xTF32): C[M,N] = A[M,K] * B[N,K]^T, fp32-accurate.
// Tile 128x128x32, 256 threads = 8 warps (2 in M x 4 in N).
// ---------------------------------------------------------------------------
#define SMEM_LD 36

__global__ __launch_bounds__(256, 1)
void tgemm_nt_kernel(float* __restrict__ C,
                     const float* __restrict__ A,
                     const float* __restrict__ B,
                     int M, int N, int K,
                     const float* __restrict__ residual,
                     const float* __restrict__ gate)
{
    __shared__ float As[128 * SMEM_LD];
    __shared__ float Bs[128 * SMEM_LD];

    const int t    = threadIdx.x;
    const int lane = t & 31;
    const int warp = t >> 5;
    const int wM   = (warp & 1) * 64;
    const int wN   = (warp >> 1) * 32;
    const int g    = lane >> 2;
    const int tg   = lane & 3;
    const int mBase = blockIdx.y * 128;
    const int nBase = blockIdx.x * 128;

    float acc[4][4][4];
#pragma unroll
    for (int mt = 0; mt < 4; mt++)
#pragma unroll
        for (int nt = 0; nt < 4; nt++)
#pragma unroll
            for (int r = 0; r < 4; r++) acc[mt][nt][r] = 0.0f;

    float4 av[4], bv[4];
#pragma unroll
    for (int i = 0; i < 4; i++) {
        const int f4i = t + i * 256;
        const int row = f4i >> 3;
        const int kc  = (f4i & 7) * 4;
        av[i] = *(const float4*)(A + (size_t)(mBase + row) * K + kc);
        bv[i] = *(const float4*)(B + (size_t)(nBase + row) * K + kc);
    }

    for (int k0 = 0; k0 < K; k0 += 32) {
#pragma unroll
        for (int i = 0; i < 4; i++) {
            const int f4i = t + i * 256;
            const int row = f4i >> 3;
            const int kc  = (f4i & 7) * 4;
            *(float4*)&As[row * SMEM_LD + kc] = av[i];
            *(float4*)&Bs[row * SMEM_LD + kc] = bv[i];
        }
        __syncthreads();

        if (k0 + 32 < K) {
#pragma unroll
            for (int i = 0; i < 4; i++) {
                const int f4i = t + i * 256;
                const int row = f4i >> 3;
                const int kc  = (f4i & 7) * 4;
                av[i] = *(const float4*)(A + (size_t)(mBase + row) * K + k0 + 32 + kc);
                bv[i] = *(const float4*)(B + (size_t)(nBase + row) * K + k0 + 32 + kc);
            }
        }

#pragma unroll
        for (int k8 = 0; k8 < 4; k8++) {
            const int kk = k8 * 8 + tg;

            unsigned Ab[4][4], Asm[4][4];
#pragma unroll
            for (int mt = 0; mt < 4; mt++) {
                const int r0 = wM + mt * 16 + g;
                float a0 = As[r0 * SMEM_LD + kk];
                float a1 = As[(r0 + 8) * SMEM_LD + kk];
                float a2 = As[r0 * SMEM_LD + kk + 4];
                float a3 = As[(r0 + 8) * SMEM_LD + kk + 4];
                Ab[mt][0] = f2tf32(a0);
                Ab[mt][1] = f2tf32(a1);
                Ab[mt][2] = f2tf32(a2);
                Ab[mt][3] = f2tf32(a3);
                Asm[mt][0] = __float_as_uint(a0 - __uint_as_float(Ab[mt][0]));
                Asm[mt][1] = __float_as_uint(a1 - __uint_as_float(Ab[mt][1]));
                Asm[mt][2] = __float_as_uint(a2 - __uint_as_float(Ab[mt][2]));
                Asm[mt][3] = __float_as_uint(a3 - __uint_as_float(Ab[mt][3]));
            }

            unsigned Bb[4][2], Bsm[4][2];
#pragma unroll
            for (int nt = 0; nt < 4; nt++) {
                const int n0 = wN + nt * 8 + g;
                float b0 = Bs[n0 * SMEM_LD + kk];
                float b1 = Bs[n0 * SMEM_LD + kk + 4];
                Bb[nt][0] = f2tf32(b0);
                Bb[nt][1] = f2tf32(b1);
                Bsm[nt][0] = __float_as_uint(b0 - __uint_as_float(Bb[nt][0]));
                Bsm[nt][1] = __float_as_uint(b1 - __uint_as_float(Bb[nt][1]));
            }

#pragma unroll
            for (int mt = 0; mt < 4; mt++)
#pragma unroll
                for (int nt = 0; nt < 4; nt++)
                    mma_tf32(acc[mt][nt], Ab[mt], Bb[nt]);
#pragma unroll
            for (int mt = 0; mt < 4; mt++)
#pragma unroll
                for (int nt = 0; nt < 4; nt++)
                    mma_tf32(acc[mt][nt], Ab[mt], Bsm[nt]);
#pragma unroll
            for (int mt = 0; mt < 4; mt++)
#pragma unroll
                for (int nt = 0; nt < 4; nt++)
                    mma_tf32(acc[mt][nt], Asm[mt], Bb[nt]);
        }
        __syncthreads();
    }

#pragma unroll
    for (int mt = 0; mt < 4; mt++) {
#pragma unroll
        for (int nt = 0; nt < 4; nt++) {
            const int row = mBase + wM + mt * 16 + g;
            const int col = nBase + wN + nt * 8 + 2 * tg;
            float v0 = acc[mt][nt][0], v1 = acc[mt][nt][1];
            float v2 = acc[mt][nt][2], v3 = acc[mt][nt][3];
            if (gate != nullptr) {
                const float g0 = gate[col], g1 = gate[col + 1];
                v0 = residual[(size_t)row * N + col]           + g0 * v0;
                v1 = residual[(size_t)row * N + col + 1]       + g1 * v1;
                v2 = residual[(size_t)(row + 8) * N + col]     + g0 * v2;
                v3 = residual[(size_t)(row + 8) * N + col + 1] + g1 * v3;
            }
            *(float2*)&C[(size_t)row * N + col]       = make_float2(v0, v1);
            *(float2*)&C[(size_t)(row + 8) * N + col] = make_float2(v2, v3);
        }
    }
}

// ---------------------------------------------------------------------------
// RoPE: in-place on q (offset 0) and k (offset D_MODEL) inside g_qkv.
// ---------------------------------------------------------------------------
__global__ void rope_kernel(float* __restrict__ qkv)
{
    const int idx = blockIdx.x * blockDim.x + threadIdx.x;
    if (idx >= S_LEN * NH * 32) return;
    const int i = idx & 31;
    const int h = (idx >> 5) & 31;
    const int s = idx >> 10;

    const float expo = (float)(2 * i) / 64.0f;
    const float invf = 1.0f / powf(10000.0f, expo);
    const float ang  = (float)s * invf;
    const float c  = cosf(ang);
    const float sn = sinf(ang);

    const size_t qb = (size_t)s * QKV_COLS + (size_t)h * DH;
    const size_t kb = qb + D_MODEL;

    const float q1 = qkv[qb + i],  q2 = qkv[qb + i + 32];
    const float k1 = qkv[kb + i],  k2 = qkv[kb + i + 32];
    qkv[qb + i]      = q1 * c - q2 * sn;
    qkv[qb + i + 32] = q2 * c + q1 * sn;
    qkv[kb + i]      = k1 * c - k2 * sn;
    qkv[kb + i + 32] = k2 * c + k1 * sn;
}

// ---------------------------------------------------------------------------
// Tensor-core causal flash attention. CTA = 128 thr (4 warps) per
// (64-query tile, head). Warp w owns query rows [16w, 16w+16).
// S = Q K^T in 3xTF32 (fp32-accurate logits); O += P V in 1-pass tf32.
// Smem stride 72 floats: every fragment access pattern is (8g+tg)-bank,
// conflict-free. K buffer is reused for P (P fragments are warp-local).
// ---------------------------------------------------------------------------
#define AST 72   // attention smem row stride (floats)

__global__ __launch_bounds__(128)
void attn_tc_kernel(float* __restrict__ out, const float* __restrict__ qkv)
{
    extern __shared__ float sm[];
    float*    Qs  = sm;                        // [64][AST]
    float*    KPs = sm + 64 * AST;             // K tile, then P
    unsigned* Vsu = (unsigned*)(sm + 2 * 64 * AST);  // V tile pre-cvt to tf32

    const int t    = threadIdx.x;
    const int lane = t & 31;
    const int warp = t >> 5;
    const int g    = lane >> 2;
    const int tg   = lane & 3;
    const int wq   = warp * 16;
    const int qb   = blockIdx.x;
    const int h    = blockIdx.y;
    const int qBase = qb * 64;

    // Load Q tile [64][64] -> Qs
    for (int i = t; i < 1024; i += 128) {
        const int row = i >> 4;
        const int dc  = (i & 15) * 4;
        float4 v = *(const float4*)&qkv[(size_t)(qBase + row) * QKV_COLS + h * DH + dc];
        *(float4*)&Qs[row * AST + dc] = v;
    }

    float m0 = -1e30f, m1 = -1e30f, l0 = 0.0f, l1 = 0.0f;
    float o[8][4];
#pragma unroll
    for (int nt = 0; nt < 8; nt++)
#pragma unroll
        for (int r = 0; r < 4; r++) o[nt][r] = 0.0f;

    __syncthreads();

    const float scale = 0.125f;
    const int r0g = qBase + wq + g;      // this thread's global query rows
    const int r1g = r0g + 8;

    for (int kb = 0; kb <= qb; kb++) {
        const int kBase = kb * 64;

        // Load K (float) and V (pre-converted tf32)
        for (int i = t; i < 1024; i += 128) {
            const int row = i >> 4;
            const int dc  = (i & 15) * 4;
            const size_t base = (size_t)(kBase + row) * QKV_COLS + h * DH + dc;
            float4 kv = *(const float4*)&qkv[base + D_MODEL];
            float4 vv = *(const float4*)&qkv[base + 2 * D_MODEL];
            *(float4*)&KPs[row * AST + dc] = kv;
            uint4 vu = make_uint4(f2tf32(vv.x), f2tf32(vv.y), f2tf32(vv.z), f2tf32(vv.w));
            *(uint4*)&Vsu[row * AST + dc] = vu;
        }
        __syncthreads();

        // ---- S = Q K^T (3xTF32) ----
        float s[8][4];
#pragma unroll
        for (int nt = 0; nt < 8; nt++)
#pragma unroll
            for (int r = 0; r < 4; r++) s[nt][r] = 0.0f;

#pragma unroll
        for (int kt = 0; kt < 8; kt++) {
            const int kk = kt * 8;
            float a0 = Qs[(wq + g) * AST + kk + tg];
            float a1 = Qs[(wq + g + 8) * AST + kk + tg];
            float a2 = Qs[(wq + g) * AST + kk + tg + 4];
            float a3 = Qs[(wq + g + 8) * AST + kk + tg + 4];
            unsigned Ab[4] = { f2tf32(a0), f2tf32(a1), f2tf32(a2), f2tf32(a3) };
            unsigned Asm[4] = {
                __float_as_uint(a0 - __uint_as_float(Ab[0])),
                __float_as_uint(a1 - __uint_as_float(Ab[1])),
                __float_as_uint(a2 - __uint_as_float(Ab[2])),
                __float_as_uint(a3 - __uint_as_float(Ab[3])) };
#pragma unroll
            for (int nt = 0; nt < 8; nt++) {
                float b0 = KPs[(g + 8 * nt) * AST + kk + tg];
                float b1 = KPs[(g + 8 * nt) * AST + kk + tg + 4];
                unsigned Bb[2]  = { f2tf32(b0), f2tf32(b1) };
                unsigned Bsm[2] = {
                    __float_as_uint(b0 - __uint_as_float(Bb[0])),
                    __float_as_uint(b1 - __uint_as_float(Bb[1])) };
                mma_tf32(s[nt], Ab, Bb);
                mma_tf32(s[nt], Ab, Bsm);
                mma_tf32(s[nt], Asm, Bb);
            }
        }
        __syncthreads();   // all warps done reading K before P overwrites it

        // ---- scale + causal mask ----
#pragma unroll
        for (int nt = 0; nt < 8; nt++) {
            const int c0 = kBase + 8 * nt + 2 * tg;
            s[nt][0] *= scale; s[nt][1] *= scale;
            s[nt][2] *= scale; s[nt][3] *= scale;
            if (kb == qb) {
                if (c0     > r0g) s[nt][0] = -1e30f;
                if (c0 + 1 > r0g) s[nt][1] = -1e30f;
                if (c0     > r1g) s[nt][2] = -1e30f;
                if (c0 + 1 > r1g) s[nt][3] = -1e30f;
            }
        }

        // ---- online softmax (rows r0g, r1g; reduce across the quad) ----
        float mx0 = -1e30f, mx1 = -1e30f;
#pragma unroll
        for (int nt = 0; nt < 8; nt++) {
            mx0 = fmaxf(mx0, fmaxf(s[nt][0], s[nt][1]));
            mx1 = fmaxf(mx1, fmaxf(s[nt][2], s[nt][3]));
        }
        mx0 = fmaxf(mx0, __shfl_xor_sync(0xffffffffu, mx0, 1));
        mx0 = fmaxf(mx0, __shfl_xor_sync(0xffffffffu, mx0, 2));
        mx1 = fmaxf(mx1, __shfl_xor_sync(0xffffffffu, mx1, 1));
        mx1 = fmaxf(mx1, __shfl_xor_sync(0xffffffffu, mx1, 2));

        const float mn0 = fmaxf(m0, mx0);
        const float mn1 = fmaxf(m1, mx1);
        const float cr0 = __expf(m0 - mn0);
        const float cr1 = __expf(m1 - mn1);
        m0 = mn0; m1 = mn1;

        float ls0 = 0.0f, ls1 = 0.0f;
#pragma unroll
        for (int nt = 0; nt < 8; nt++) {
            s[nt][0] = __expf(s[nt][0] - mn0); ls0 += s[nt][0];
            s[nt][1] = __expf(s[nt][1] - mn0); ls0 += s[nt][1];
            s[nt][2] = __expf(s[nt][2] - mn1); ls1 += s[nt][2];
            s[nt][3] = __expf(s[nt][3] - mn1); ls1 += s[nt][3];
        }
        ls0 += __shfl_xor_sync(0xffffffffu, ls0, 1);
        ls0 += __shfl_xor_sync(0xffffffffu, ls0, 2);
        ls1 += __shfl_xor_sync(0xffffffffu, ls1, 1);
        ls1 += __shfl_xor_sync(0xffffffffu, ls1, 2);
        l0 = l0 * cr0 + ls0;
        l1 = l1 * cr1 + ls1;

#pragma unroll
        for (int nt = 0; nt < 8; nt++) {
            o[nt][0] *= cr0; o[nt][1] *= cr0;
            o[nt][2] *= cr1; o[nt][3] *= cr1;
        }

        // ---- write P into KPs (warp-local rows) ----
#pragma unroll
        for (int nt = 0; nt < 8; nt++) {
            *(float2*)&KPs[(wq + g) * AST + 8 * nt + 2 * tg] =
                make_float2(s[nt][0], s[nt][1]);
            *(float2*)&KPs[(wq + g + 8) * AST + 8 * nt + 2 * tg] =
                make_float2(s[nt][2], s[nt][3]);
        }
        __syncwarp();

        // ---- O += P V (tf32 single pass) ----
#pragma unroll
        for (int kt = 0; kt < 8; kt++) {
            unsigned Ab[4] = {
                f2tf32(KPs[(wq + g) * AST + kt * 8 + tg]),
                f2tf32(KPs[(wq + g + 8) * AST + kt * 8 + tg]),
                f2tf32(KPs[(wq + g) * AST + kt * 8 + tg + 4]),
                f2tf32(KPs[(wq + g + 8) * AST + kt * 8 + tg + 4]) };
#pragma unroll
            for (int nt = 0; nt < 8; nt++) {
                unsigned Bb[2] = {
                    Vsu[(kt * 8 + tg) * AST + 8 * nt + g],
                    Vsu[(kt * 8 + tg + 4) * AST + 8 * nt + g] };
                mma_tf32(o[nt], Ab, Bb);
            }
        }
        __syncthreads();   // before next tile overwrites KPs / Vsu
    }

    // ---- normalize + store ----
    const float inv0 = 1.0f / l0;
    const float inv1 = 1.0f / l1;
#pragma unroll
    for (int nt = 0; nt < 8; nt++) {
        const int d = h * DH + 8 * nt + 2 * tg;
        *(float2*)&out[(size_t)r0g * D_MODEL + d] =
            make_float2(o[nt][0] * inv0, o[nt][1] * inv0);
        *(float2*)&out[(size_t)r1g * D_MODEL + d] =
            make_float2(o[nt][2] * inv1, o[nt][3] * inv1);
    }
}

// ---------------------------------------------------------------------------
// Launch
// ---------------------------------------------------------------------------
extern "C" void kernel_launch(void* const* d_in, const int* in_sizes, int n_in,
                              void* d_out, int out_size)
{
    const float* x    = (const float*)d_in[0];
    const float* Wqkv = (const float*)d_in[1];
    const float* Wo   = (const float*)d_in[2];
    const float* gate = (const float*)d_in[3];
    float* out = (float*)d_out;

    float* qkv  = nullptr;
    float* attn = nullptr;
    cudaGetSymbolAddress((void**)&qkv,  g_qkv);
    cudaGetSymbolAddress((void**)&attn, g_attn);

    const int attnSmem = 3 * 64 * AST * (int)sizeof(float);   // 55296 B
    cudaFuncSetAttribute(attn_tc_kernel,
                         cudaFuncAttributeMaxDynamicSharedMemorySize, attnSmem);

    // 1) QKV projection
    tgemm_nt_kernel<<<dim3(QKV_COLS / 128, S_LEN / 128), 256>>>(
        qkv, x, Wqkv, S_LEN, QKV_COLS, D_MODEL, nullptr, nullptr);

    // 2) RoPE in place on q, k
    rope_kernel<<<(S_LEN * NH * 32) / 256, 256>>>(qkv);

    // 3) Causal attention (tensor cores)
    attn_tc_kernel<<<dim3(S_LEN / 64, NH), 128, attnSmem>>>(attn, qkv);

    // 4) Output projection + gated residual
    tgemm_nt_kernel<<<dim3(D_MODEL / 128, S_LEN / 128), 256>>>(
        out, attn, Wo, S_LEN, D_MODEL, D_MODEL, x, gate);
}

// round 17
// speedup vs baseline: 1.1573x; 1.1573x over previous
#include <cuda_runtime.h>
#include <math.h>

#define S_LEN   2048
#define D_MODEL 2048
#define NH      32
#define DH      64
#define QKV_COLS (3 * D_MODEL)   // 6144

// Scratch (allocation-free rule: static __device__ globals)
__device__ float g_qkv[(size_t)S_LEN * QKV_COLS];   // [S, 3, H, Dh]
__device__ float g_attn[(size_t)S_LEN * D_MODEL];   // [S, H*Dh]

// ---------------------------------------------------------------------------
// tf32 helpers
// ---------------------------------------------------------------------------
__device__ __forceinline__ unsigned f2tf32(float x) {
    unsigned r;
    asm("cvt.rna.tf32.f32 %0, %1;" : "=r"(r) : "f"(x));
    return r;
}

__device__ __forceinline__ void mma_tf32(float* d, const unsigned* a, const unsigned* b) {
    asm volatile(
        "mma.sync.aligned.m16n8k8.row.col.f32.tf32.tf32.f32 "
        "{%0,%1,%2,%3}, {%4,%5,%6,%7}, {%8,%9}, {%0,%1,%2,%3};\n"
        : "+f"(d[0]), "+f"(d[1]), "+f"(d[2]), "+f"(d[3])
        : "r"(a[0]), "r"(a[1]), "r"(a[2]), "r"(a[3]), "r"(b[0]), "r"(b[1]));
}

// ---------------------------------------------------------------------------
// Tensor-core GEMM NT: C[M,N] = A[M,K] * B[N,K]^T.
// THREE=1: 3xTF32 (fp32-accurate); THREE=0: single-pass tf32.
// hi/lo split happens at smem-store time; inner loop is pure LDS + MMA.
// Tile 128x128x32, 256 threads = 8 warps (2 in M x 4 in N).
// ---------------------------------------------------------------------------
#define SMEM_LD 36   // padded K-stride: conflict-free for all fragment patterns

template<int THREE>
__global__ __launch_bounds__(256, 1)
void tgemm_nt_kernel(float* __restrict__ C,
                     const float* __restrict__ A,
                     const float* __restrict__ B,
                     int M, int N, int K,
                     const float* __restrict__ residual,
                     const float* __restrict__ gate)
{
    extern __shared__ unsigned smg[];
    unsigned* Ah = smg;                       // hi tiles (tf32)
    unsigned* Bh = Ah + 128 * SMEM_LD;
    unsigned* Al = Bh + 128 * SMEM_LD;        // lo tiles (fp32 residual bits)
    unsigned* Bl = Al + 128 * SMEM_LD;        // (only touched when THREE)

    const int t    = threadIdx.x;
    const int lane = t & 31;
    const int warp = t >> 5;
    const int wM   = (warp & 1) * 64;
    const int wN   = (warp >> 1) * 32;
    const int g    = lane >> 2;
    const int tg   = lane & 3;
    const int mBase = blockIdx.y * 128;
    const int nBase = blockIdx.x * 128;

    float acc[4][4][4];
#pragma unroll
    for (int mt = 0; mt < 4; mt++)
#pragma unroll
        for (int nt = 0; nt < 4; nt++)
#pragma unroll
            for (int r = 0; r < 4; r++) acc[mt][nt][r] = 0.0f;

    float4 av[4], bv[4];
#pragma unroll
    for (int i = 0; i < 4; i++) {
        const int f4i = t + i * 256;
        const int row = f4i >> 3;
        const int kc  = (f4i & 7) * 4;
        av[i] = *(const float4*)(A + (size_t)(mBase + row) * K + kc);
        bv[i] = *(const float4*)(B + (size_t)(nBase + row) * K + kc);
    }

    for (int k0 = 0; k0 < K; k0 += 32) {
        // Split + store prefetched tile to smem
#pragma unroll
        for (int i = 0; i < 4; i++) {
            const int f4i = t + i * 256;
            const int row = f4i >> 3;
            const int kc  = (f4i & 7) * 4;
            uint4 ah, bh;
            ah.x = f2tf32(av[i].x); ah.y = f2tf32(av[i].y);
            ah.z = f2tf32(av[i].z); ah.w = f2tf32(av[i].w);
            bh.x = f2tf32(bv[i].x); bh.y = f2tf32(bv[i].y);
            bh.z = f2tf32(bv[i].z); bh.w = f2tf32(bv[i].w);
            *(uint4*)&Ah[row * SMEM_LD + kc] = ah;
            *(uint4*)&Bh[row * SMEM_LD + kc] = bh;
            if (THREE) {
                uint4 al, bl;
                al.x = __float_as_uint(av[i].x - __uint_as_float(ah.x));
                al.y = __float_as_uint(av[i].y - __uint_as_float(ah.y));
                al.z = __float_as_uint(av[i].z - __uint_as_float(ah.z));
                al.w = __float_as_uint(av[i].w - __uint_as_float(ah.w));
                bl.x = __float_as_uint(bv[i].x - __uint_as_float(bh.x));
                bl.y = __float_as_uint(bv[i].y - __uint_as_float(bh.y));
                bl.z = __float_as_uint(bv[i].z - __uint_as_float(bh.z));
                bl.w = __float_as_uint(bv[i].w - __uint_as_float(bh.w));
                *(uint4*)&Al[row * SMEM_LD + kc] = al;
                *(uint4*)&Bl[row * SMEM_LD + kc] = bl;
            }
        }
        __syncthreads();

        // Prefetch next k-tile
        if (k0 + 32 < K) {
#pragma unroll
            for (int i = 0; i < 4; i++) {
                const int f4i = t + i * 256;
                const int row = f4i >> 3;
                const int kc  = (f4i & 7) * 4;
                av[i] = *(const float4*)(A + (size_t)(mBase + row) * K + k0 + 32 + kc);
                bv[i] = *(const float4*)(B + (size_t)(nBase + row) * K + k0 + 32 + kc);
            }
        }

#pragma unroll
        for (int k8 = 0; k8 < 4; k8++) {
            const int kk = k8 * 8 + tg;

            unsigned Abf[4][4], Alf[4][4];
#pragma unroll
            for (int mt = 0; mt < 4; mt++) {
                const int r0 = wM + mt * 16 + g;
                Abf[mt][0] = Ah[r0 * SMEM_LD + kk];
                Abf[mt][1] = Ah[(r0 + 8) * SMEM_LD + kk];
                Abf[mt][2] = Ah[r0 * SMEM_LD + kk + 4];
                Abf[mt][3] = Ah[(r0 + 8) * SMEM_LD + kk + 4];
                if (THREE) {
                    Alf[mt][0] = Al[r0 * SMEM_LD + kk];
                    Alf[mt][1] = Al[(r0 + 8) * SMEM_LD + kk];
                    Alf[mt][2] = Al[r0 * SMEM_LD + kk + 4];
                    Alf[mt][3] = Al[(r0 + 8) * SMEM_LD + kk + 4];
                }
            }

            unsigned Bbf[4][2], Blf[4][2];
#pragma unroll
            for (int nt = 0; nt < 4; nt++) {
                const int n0 = wN + nt * 8 + g;
                Bbf[nt][0] = Bh[n0 * SMEM_LD + kk];
                Bbf[nt][1] = Bh[n0 * SMEM_LD + kk + 4];
                if (THREE) {
                    Blf[nt][0] = Bl[n0 * SMEM_LD + kk];
                    Blf[nt][1] = Bl[n0 * SMEM_LD + kk + 4];
                }
            }

#pragma unroll
            for (int mt = 0; mt < 4; mt++)
#pragma unroll
                for (int nt = 0; nt < 4; nt++)
                    mma_tf32(acc[mt][nt], Abf[mt], Bbf[nt]);
            if (THREE) {
#pragma unroll
                for (int mt = 0; mt < 4; mt++)
#pragma unroll
                    for (int nt = 0; nt < 4; nt++)
                        mma_tf32(acc[mt][nt], Abf[mt], Blf[nt]);
#pragma unroll
                for (int mt = 0; mt < 4; mt++)
#pragma unroll
                    for (int nt = 0; nt < 4; nt++)
                        mma_tf32(acc[mt][nt], Alf[mt], Bbf[nt]);
            }
        }
        __syncthreads();
    }

#pragma unroll
    for (int mt = 0; mt < 4; mt++) {
#pragma unroll
        for (int nt = 0; nt < 4; nt++) {
            const int row = mBase + wM + mt * 16 + g;
            const int col = nBase + wN + nt * 8 + 2 * tg;
            float v0 = acc[mt][nt][0], v1 = acc[mt][nt][1];
            float v2 = acc[mt][nt][2], v3 = acc[mt][nt][3];
            if (gate != nullptr) {
                const float g0 = gate[col], g1 = gate[col + 1];
                v0 = residual[(size_t)row * N + col]           + g0 * v0;
                v1 = residual[(size_t)row * N + col + 1]       + g1 * v1;
                v2 = residual[(size_t)(row + 8) * N + col]     + g0 * v2;
                v3 = residual[(size_t)(row + 8) * N + col + 1] + g1 * v3;
            }
            *(float2*)&C[(size_t)row * N + col]       = make_float2(v0, v1);
            *(float2*)&C[(size_t)(row + 8) * N + col] = make_float2(v2, v3);
        }
    }
}

// ---------------------------------------------------------------------------
// RoPE: in-place on q (offset 0) and k (offset D_MODEL) inside g_qkv.
// ---------------------------------------------------------------------------
__global__ void rope_kernel(float* __restrict__ qkv)
{
    const int idx = blockIdx.x * blockDim.x + threadIdx.x;
    if (idx >= S_LEN * NH * 32) return;
    const int i = idx & 31;
    const int h = (idx >> 5) & 31;
    const int s = idx >> 10;

    const float expo = (float)(2 * i) / 64.0f;
    const float invf = 1.0f / powf(10000.0f, expo);
    const float ang  = (float)s * invf;
    const float c  = cosf(ang);
    const float sn = sinf(ang);

    const size_t qb = (size_t)s * QKV_COLS + (size_t)h * DH;
    const size_t kb = qb + D_MODEL;

    const float q1 = qkv[qb + i],  q2 = qkv[qb + i + 32];
    const float k1 = qkv[kb + i],  k2 = qkv[kb + i + 32];
    qkv[qb + i]      = q1 * c - q2 * sn;
    qkv[qb + i + 32] = q2 * c + q1 * sn;
    qkv[kb + i]      = k1 * c - k2 * sn;
    qkv[kb + i + 32] = k2 * c + k1 * sn;
}

// ---------------------------------------------------------------------------
// Tensor-core causal flash attention, single-pass tf32 QK and PV.
// CTA = 128 thr (4 warps) per (64-query tile, head); warp w owns rows
// [16w,16w+16). Q/K/V/P all pre-converted to tf32 at smem-store time,
// so the mma loops are pure LDS + MMA. Stride-72 smem, conflict-free.
// ---------------------------------------------------------------------------
#define AST 72   // attention smem row stride (elements)

__global__ __launch_bounds__(128)
void attn_tc_kernel(float* __restrict__ out, const float* __restrict__ qkv)
{
    extern __shared__ unsigned smu[];
    unsigned* Qs  = smu;                  // Q (tf32)
    unsigned* KPs = smu + 64 * AST;       // K tile (tf32), then P (tf32)
    unsigned* Vsu = smu + 2 * 64 * AST;   // V (tf32)

    const int t    = threadIdx.x;
    const int lane = t & 31;
    const int warp = t >> 5;
    const int g    = lane >> 2;
    const int tg   = lane & 3;
    const int wq   = warp * 16;
    const int qb   = blockIdx.x;
    const int h    = blockIdx.y;
    const int qBase = qb * 64;

    // Load Q tile [64][64] -> tf32 smem
    for (int i = t; i < 1024; i += 128) {
        const int row = i >> 4;
        const int dc  = (i & 15) * 4;
        float4 v = *(const float4*)&qkv[(size_t)(qBase + row) * QKV_COLS + h * DH + dc];
        uint4 u = make_uint4(f2tf32(v.x), f2tf32(v.y), f2tf32(v.z), f2tf32(v.w));
        *(uint4*)&Qs[row * AST + dc] = u;
    }

    float m0 = -1e30f, m1 = -1e30f, l0 = 0.0f, l1 = 0.0f;
    float o[8][4];
#pragma unroll
    for (int nt = 0; nt < 8; nt++)
#pragma unroll
        for (int r = 0; r < 4; r++) o[nt][r] = 0.0f;

    __syncthreads();

    const float scale = 0.125f;
    const int r0g = qBase + wq + g;
    const int r1g = r0g + 8;

    for (int kb = 0; kb <= qb; kb++) {
        const int kBase = kb * 64;

        // Load K and V tiles (both converted to tf32)
        for (int i = t; i < 1024; i += 128) {
            const int row = i >> 4;
            const int dc  = (i & 15) * 4;
            const size_t base = (size_t)(kBase + row) * QKV_COLS + h * DH + dc;
            float4 kv = *(const float4*)&qkv[base + D_MODEL];
            float4 vv = *(const float4*)&qkv[base + 2 * D_MODEL];
            uint4 ku = make_uint4(f2tf32(kv.x), f2tf32(kv.y), f2tf32(kv.z), f2tf32(kv.w));
            uint4 vu = make_uint4(f2tf32(vv.x), f2tf32(vv.y), f2tf32(vv.z), f2tf32(vv.w));
            *(uint4*)&KPs[row * AST + dc] = ku;
            *(uint4*)&Vsu[row * AST + dc] = vu;
        }
        __syncthreads();

        // ---- S = Q K^T (single-pass tf32) ----
        float s[8][4];
#pragma unroll
        for (int nt = 0; nt < 8; nt++)
#pragma unroll
            for (int r = 0; r < 4; r++) s[nt][r] = 0.0f;

#pragma unroll
        for (int kt = 0; kt < 8; kt++) {
            const int kk = kt * 8;
            unsigned Ab[4] = {
                Qs[(wq + g) * AST + kk + tg],
                Qs[(wq + g + 8) * AST + kk + tg],
                Qs[(wq + g) * AST + kk + tg + 4],
                Qs[(wq + g + 8) * AST + kk + tg + 4] };
#pragma unroll
            for (int nt = 0; nt < 8; nt++) {
                unsigned Bb[2] = {
                    KPs[(g + 8 * nt) * AST + kk + tg],
                    KPs[(g + 8 * nt) * AST + kk + tg + 4] };
                mma_tf32(s[nt], Ab, Bb);
            }
        }
        __syncthreads();   // all warps done reading K before P overwrites it

        // ---- scale + causal mask ----
#pragma unroll
        for (int nt = 0; nt < 8; nt++) {
            const int c0 = kBase + 8 * nt + 2 * tg;
            s[nt][0] *= scale; s[nt][1] *= scale;
            s[nt][2] *= scale; s[nt][3] *= scale;
            if (kb == qb) {
                if (c0     > r0g) s[nt][0] = -1e30f;
                if (c0 + 1 > r0g) s[nt][1] = -1e30f;
                if (c0     > r1g) s[nt][2] = -1e30f;
                if (c0 + 1 > r1g) s[nt][3] = -1e30f;
            }
        }

        // ---- online softmax ----
        float mx0 = -1e30f, mx1 = -1e30f;
#pragma unroll
        for (int nt = 0; nt < 8; nt++) {
            mx0 = fmaxf(mx0, fmaxf(s[nt][0], s[nt][1]));
            mx1 = fmaxf(mx1, fmaxf(s[nt][2], s[nt][3]));
        }
        mx0 = fmaxf(mx0, __shfl_xor_sync(0xffffffffu, mx0, 1));
        mx0 = fmaxf(mx0, __shfl_xor_sync(0xffffffffu, mx0, 2));
        mx1 = fmaxf(mx1, __shfl_xor_sync(0xffffffffu, mx1, 1));
        mx1 = fmaxf(mx1, __shfl_xor_sync(0xffffffffu, mx1, 2));

        const float mn0 = fmaxf(m0, mx0);
        const float mn1 = fmaxf(m1, mx1);
        const float cr0 = __expf(m0 - mn0);
        const float cr1 = __expf(m1 - mn1);
        m0 = mn0; m1 = mn1;

        float ls0 = 0.0f, ls1 = 0.0f;
#pragma unroll
        for (int nt = 0; nt < 8; nt++) {
            s[nt][0] = __expf(s[nt][0] - mn0); ls0 += s[nt][0];
            s[nt][1] = __expf(s[nt][1] - mn0); ls0 += s[nt][1];
            s[nt][2] = __expf(s[nt][2] - mn1); ls1 += s[nt][2];
            s[nt][3] = __expf(s[nt][3] - mn1); ls1 += s[nt][3];
        }
        ls0 += __shfl_xor_sync(0xffffffffu, ls0, 1);
        ls0 += __shfl_xor_sync(0xffffffffu, ls0, 2);
        ls1 += __shfl_xor_sync(0xffffffffu, ls1, 1);
        ls1 += __shfl_xor_sync(0xffffffffu, ls1, 2);
        l0 = l0 * cr0 + ls0;
        l1 = l1 * cr1 + ls1;

#pragma unroll
        for (int nt = 0; nt < 8; nt++) {
            o[nt][0] *= cr0; o[nt][1] *= cr0;
            o[nt][2] *= cr1; o[nt][3] *= cr1;
        }

        // ---- write P (tf32) into KPs, warp-local rows ----
#pragma unroll
        for (int nt = 0; nt < 8; nt++) {
            *(uint2*)&KPs[(wq + g) * AST + 8 * nt + 2 * tg] =
                make_uint2(f2tf32(s[nt][0]), f2tf32(s[nt][1]));
            *(uint2*)&KPs[(wq + g + 8) * AST + 8 * nt + 2 * tg] =
                make_uint2(f2tf32(s[nt][2]), f2tf32(s[nt][3]));
        }
        __syncwarp();

        // ---- O += P V (single-pass tf32) ----
#pragma unroll
        for (int kt = 0; kt < 8; kt++) {
            unsigned Ab[4] = {
                KPs[(wq + g) * AST + kt * 8 + tg],
                KPs[(wq + g + 8) * AST + kt * 8 + tg],
                KPs[(wq + g) * AST + kt * 8 + tg + 4],
                KPs[(wq + g + 8) * AST + kt * 8 + tg + 4] };
#pragma unroll
            for (int nt = 0; nt < 8; nt++) {
                unsigned Bb[2] = {
                    Vsu[(kt * 8 + tg) * AST + 8 * nt + g],
                    Vsu[(kt * 8 + tg + 4) * AST + 8 * nt + g] };
                mma_tf32(o[nt], Ab, Bb);
            }
        }
        __syncthreads();   // before next tile overwrites KPs / Vsu
    }

    // ---- normalize + store ----
    const float inv0 = 1.0f / l0;
    const float inv1 = 1.0f / l1;
#pragma unroll
    for (int nt = 0; nt < 8; nt++) {
        const int d = h * DH + 8 * nt + 2 * tg;
        *(float2*)&out[(size_t)r0g * D_MODEL + d] =
            make_float2(o[nt][0] * inv0, o[nt][1] * inv0);
        *(float2*)&out[(size_t)r1g * D_MODEL + d] =
            make_float2(o[nt][2] * inv1, o[nt][3] * inv1);
    }
}

// ---------------------------------------------------------------------------
// Launch
// ---------------------------------------------------------------------------
extern "C" void kernel_launch(void* const* d_in, const int* in_sizes, int n_in,
                              void* d_out, int out_size)
{
    const float* x    = (const float*)d_in[0];
    const float* Wqkv = (const float*)d_in[1];
    const float* Wo   = (const float*)d_in[2];
    const float* gate = (const float*)d_in[3];
    float* out = (float*)d_out;

    float* qkv  = nullptr;
    float* attn = nullptr;
    cudaGetSymbolAddress((void**)&qkv,  g_qkv);
    cudaGetSymbolAddress((void**)&attn, g_attn);

    const int gemm3Smem = 4 * 128 * SMEM_LD * (int)sizeof(unsigned);  // 73728
    const int gemm1Smem = 2 * 128 * SMEM_LD * (int)sizeof(unsigned);  // 36864
    const int attnSmem  = 3 * 64 * AST * (int)sizeof(unsigned);       // 55296

    cudaFuncSetAttribute(tgemm_nt_kernel<1>,
                         cudaFuncAttributeMaxDynamicSharedMemorySize, gemm3Smem);
    cudaFuncSetAttribute(tgemm_nt_kernel<0>,
                         cudaFuncAttributeMaxDynamicSharedMemorySize, gemm1Smem);
    cudaFuncSetAttribute(attn_tc_kernel,
                         cudaFuncAttributeMaxDynamicSharedMemorySize, attnSmem);

    // 1) QKV projection (3xTF32 — feeds softmax, keep fp32-accurate)
    tgemm_nt_kernel<1><<<dim3(QKV_COLS / 128, S_LEN / 128), 256, gemm3Smem>>>(
        qkv, x, Wqkv, S_LEN, QKV_COLS, D_MODEL, nullptr, nullptr);

    // 2) RoPE in place on q, k
    rope_kernel<<<(S_LEN * NH * 32) / 256, 256>>>(qkv);

    // 3) Causal attention (tensor cores, single-pass tf32)
    attn_tc_kernel<<<dim3(S_LEN / 64, NH), 128, attnSmem>>>(attn, qkv);

    // 4) Output projection + gated residual (single-pass tf32; gate-attenuated)
    tgemm_nt_kernel<0><<<dim3(D_MODEL / 128, S_LEN / 128), 256, gemm1Smem>>>(
        out, attn, Wo, S_LEN, D_MODEL, D_MODEL, x, gate);
}